// round 2
// baseline (speedup 1.0000x reference)
#include <cuda_runtime.h>
#include <cstdint>

#define NNODES 100000
#define NEDGES 3200000
#define INDIM 256
#define HID 64
#define OUTD 32

// ---------------- scratch (static device globals; 16B+ aligned for vector ops) ----------------
__device__ __align__(128) float g_dinv[NNODES];
__device__ __align__(128) float g_h1[(size_t)NNODES * HID];
__device__ __align__(128) float g_agg1[(size_t)NNODES * HID];
__device__ __align__(128) float g_h2[(size_t)NNODES * OUTD];
__device__ __align__(128) int   g_src[NEDGES];
__device__ __align__(128) int   g_dst[NEDGES];
__device__ __align__(128) float g_norm[NEDGES];
__device__ int g_is64;

// ---------------- index dtype detection + conversion ----------------
// If edge_index is int64 (values in [0,1e5)), every odd 32-bit word is 0.
// If it is int32, odd words are src indices (prob. all-zero over 512 samples ~ 0).
__global__ void k_detect(const int* __restrict__ ei32) {
    if (blockIdx.x == 0 && threadIdx.x == 0) {
        int acc = 0;
        for (int i = 0; i < 512; i++) acc |= ei32[2 * i + 1];
        // also sample from the second half of the buffer
        for (int i = 0; i < 512; i++) acc |= ei32[2 * (NEDGES / 2 + i) + 1];
        g_is64 = (acc == 0) ? 1 : 0;
    }
}

__global__ void k_convert(const void* __restrict__ ei) {
    int e = blockIdx.x * blockDim.x + threadIdx.x;
    if (e >= NEDGES) return;
    int s, d;
    if (g_is64) {
        const long long* p = (const long long*)ei;
        s = (int)p[e];
        d = (int)p[NEDGES + e];
    } else {
        const int* p = (const int*)ei;
        s = p[e];
        d = p[NEDGES + e];
    }
    g_src[e] = s;
    g_dst[e] = d;
}

// ---------------- degree / normalization ----------------
__global__ void k_deg_init() {
    int i = blockIdx.x * blockDim.x + threadIdx.x;
    if (i < NNODES) g_dinv[i] = 1.0f;  // self-loop contributes 1
}

__global__ void k_deg_accum() {
    int e = blockIdx.x * blockDim.x + threadIdx.x;
    if (e < NEDGES) atomicAdd(&g_dinv[g_dst[e]], 1.0f);
}

__global__ void k_dinv() {
    int i = blockIdx.x * blockDim.x + threadIdx.x;
    if (i < NNODES) g_dinv[i] = rsqrtf(g_dinv[i]);  // deg >= 1 always
}

__global__ void k_edge_norm() {
    int e = blockIdx.x * blockDim.x + threadIdx.x;
    if (e < NEDGES) g_norm[e] = g_dinv[g_src[e]] * g_dinv[g_dst[e]];
}

// ---------------- GEMM: H[M,NO] = X[M,K] @ W[K,NO], shared-staged ----------------
template <int K, int NO>
__global__ void k_gemm(const float* __restrict__ X, const float* __restrict__ W,
                       float* __restrict__ H) {
    constexpr int KT  = 64;
    constexpr int CG  = NO / 16;
    constexpr int RPB = 256 / CG;

    __shared__ __align__(16) float xs[RPB * (KT + 1)];
    __shared__ __align__(16) float ws[KT * NO];

    const int tid  = threadIdx.x;
    const int row0 = blockIdx.x * RPB;
    const int r    = tid % RPB;   // consecutive lanes -> consecutive rows (pad => conflict-free)
    const int cg   = tid / RPB;   // warp-uniform column group
    const int row  = row0 + r;

    float acc[16];
#pragma unroll
    for (int j = 0; j < 16; j++) acc[j] = 0.0f;

    for (int kt = 0; kt < K; kt += KT) {
        for (int idx = tid; idx < RPB * KT; idx += 256) {
            int rr = idx / KT, kk = idx % KT;
            int grow = row0 + rr;
            xs[rr * (KT + 1) + kk] = (grow < NNODES) ? X[(size_t)grow * K + kt + kk] : 0.0f;
        }
        for (int idx = tid; idx < KT * NO; idx += 256)
            ws[idx] = W[(size_t)kt * NO + idx];
        __syncthreads();

#pragma unroll 8
        for (int k = 0; k < KT; k++) {
            float xv = xs[r * (KT + 1) + k];
            const float4* wr = reinterpret_cast<const float4*>(&ws[k * NO + cg * 16]);
            float4 w0 = wr[0], w1 = wr[1], w2 = wr[2], w3 = wr[3];
            acc[0]  += xv * w0.x;  acc[1]  += xv * w0.y;
            acc[2]  += xv * w0.z;  acc[3]  += xv * w0.w;
            acc[4]  += xv * w1.x;  acc[5]  += xv * w1.y;
            acc[6]  += xv * w1.z;  acc[7]  += xv * w1.w;
            acc[8]  += xv * w2.x;  acc[9]  += xv * w2.y;
            acc[10] += xv * w2.z;  acc[11] += xv * w2.w;
            acc[12] += xv * w3.x;  acc[13] += xv * w3.y;
            acc[14] += xv * w3.z;  acc[15] += xv * w3.w;
        }
        __syncthreads();
    }

    if (row < NNODES) {
        float4* out = reinterpret_cast<float4*>(&H[(size_t)row * NO + cg * 16]);
        out[0] = make_float4(acc[0],  acc[1],  acc[2],  acc[3]);
        out[1] = make_float4(acc[4],  acc[5],  acc[6],  acc[7]);
        out[2] = make_float4(acc[8],  acc[9],  acc[10], acc[11]);
        out[3] = make_float4(acc[12], acc[13], acc[14], acc[15]);
    }
}

// ---------------- fused accumulator init: self-loop term + bias ----------------
__global__ void k_fuse1(const float* __restrict__ b1) {
    int i = blockIdx.x * blockDim.x + threadIdx.x;
    if (i < NNODES * HID) {
        int node = i >> 6;  // /64
        int c    = i & 63;
        float dn = g_dinv[node];
        g_agg1[i] = dn * dn * g_h1[i] + __ldg(&b1[c]);
    }
}

__global__ void k_relu() {
    int i = blockIdx.x * blockDim.x + threadIdx.x;
    if (i < NNODES * HID) g_h1[i] = fmaxf(g_agg1[i], 0.0f);
}

__global__ void k_fuse2(const float* __restrict__ b2, float* __restrict__ out) {
    int i = blockIdx.x * blockDim.x + threadIdx.x;
    if (i < NNODES * OUTD) {
        int node = i >> 5;  // /32
        int c    = i & 31;
        float dn = g_dinv[node];
        out[i] = dn * dn * g_h2[i] + __ldg(&b2[c]);
    }
}

// ---------------- edge scatter: Out[dst] += norm[e] * H[src] ----------------
// NO/4 float4 chunks per edge; 16-byte vectorized reduction (red.global.add.v4.f32).
template <int NO>
__global__ void k_scatter(const float* __restrict__ H, float* __restrict__ Out) {
    constexpr int CH = NO / 4;
    int idx = blockIdx.x * blockDim.x + threadIdx.x;  // < E*CH = 51.2M, fits int
    if (idx >= NEDGES * CH) return;
    int e = idx / CH;
    int c = idx % CH;
    int s = g_src[e];
    int d = g_dst[e];
    float nrm = g_norm[e];
    float4 v = *reinterpret_cast<const float4*>(&H[(size_t)s * NO + c * 4]);
    v.x *= nrm; v.y *= nrm; v.z *= nrm; v.w *= nrm;
    float* dst = &Out[(size_t)d * NO + c * 4];
    asm volatile("red.global.add.v4.f32 [%0], {%1, %2, %3, %4};"
                 :: "l"(dst), "f"(v.x), "f"(v.y), "f"(v.z), "f"(v.w)
                 : "memory");
}

// ---------------- launch ----------------
extern "C" void kernel_launch(void* const* d_in, const int* in_sizes, int n_in,
                              void* d_out, int out_size) {
    const float* x  = (const float*)d_in[0];
    const void*  ei = d_in[1];
    const float* W1 = (const float*)d_in[2];
    const float* b1 = (const float*)d_in[3];
    const float* W2 = (const float*)d_in[4];
    const float* b2 = (const float*)d_in[5];
    float*       out = (float*)d_out;

    void *ph1, *pagg1, *ph2;
    cudaGetSymbolAddress(&ph1,   g_h1);
    cudaGetSymbolAddress(&pagg1, g_agg1);
    cudaGetSymbolAddress(&ph2,   g_h2);
    float* h1   = (float*)ph1;
    float* agg1 = (float*)pagg1;
    float* h2   = (float*)ph2;

    const int NT = 256;
    const int EB = (NEDGES + NT - 1) / NT;
    const int NB = (NNODES + NT - 1) / NT;

    // index normalization
    k_detect<<<1, 32>>>((const int*)ei);
    k_convert<<<EB, NT>>>(ei);

    // gcn_norm
    k_deg_init<<<NB, NT>>>();
    k_deg_accum<<<EB, NT>>>();
    k_dinv<<<NB, NT>>>();
    k_edge_norm<<<EB, NT>>>();

    // layer 1: h1 = X @ W1 ; agg1 = selfloop + b1 + scatter ; h1 = relu(agg1)
    k_gemm<INDIM, HID><<<(NNODES + 63) / 64, NT>>>(x, W1, h1);
    k_fuse1<<<((NNODES * HID) + NT - 1) / NT, NT>>>(b1);
    k_scatter<HID><<<((NEDGES * (HID / 4)) + NT - 1) / NT, NT>>>(h1, agg1);
    k_relu<<<((NNODES * HID) + NT - 1) / NT, NT>>>();

    // layer 2: h2 = relu1 @ W2 ; out = selfloop + b2 + scatter
    k_gemm<HID, OUTD><<<(NNODES + 127) / 128, NT>>>(h1, W2, h2);
    k_fuse2<<<((NNODES * OUTD) + NT - 1) / NT, NT>>>(b2, out);
    k_scatter<OUTD><<<((NEDGES * (OUTD / 4)) + NT - 1) / NT, NT>>>(h2, out);
}

// round 3
// speedup vs baseline: 1.6205x; 1.6205x over previous
#include <cuda_runtime.h>
#include <cstdint>

#define NNODES 100000
#define NEDGES 3200000
#define INDIM 256
#define HID 64
#define OUTD 32
#define NSCANB 98   // ceil(100000/1024)

// ---------------- scratch ----------------
__device__ __align__(128) int      g_deg[NNODES];
__device__ __align__(128) float    g_dinv[NNODES];
__device__ __align__(128) int      g_rowptr[NNODES + 1];
__device__ __align__(128) int      g_cursor[NNODES];
__device__ __align__(128) int      g_bsum[NSCANB];
__device__ __align__(128) int      g_src[NEDGES];
__device__ __align__(128) int      g_dst[NEDGES];
__device__ __align__(128) uint64_t g_csr[NEDGES];      // (norm_bits<<32) | src
__device__ __align__(128) float    g_h1[(size_t)NNODES * HID];
__device__ __align__(128) float    g_h1r[(size_t)NNODES * HID];
__device__ __align__(128) float    g_h2[(size_t)NNODES * OUTD];
__device__ int g_is64;

// ---------------- index dtype detection ----------------
__global__ void k_detect(const int* __restrict__ ei32) {
    if (threadIdx.x == 0) {
        int acc = 0;
        for (int i = 0; i < 512; i++) acc |= ei32[2 * i + 1];
        for (int i = 0; i < 512; i++) acc |= ei32[2 * (NEDGES / 2 + i) + 1];
        g_is64 = (acc == 0) ? 1 : 0;
    }
}

__global__ void k_zero_deg() {
    int i = blockIdx.x * blockDim.x + threadIdx.x;
    if (i < NNODES) g_deg[i] = 0;
}

// convert edge indices to int32 + count in-degree (edges only)
__global__ void k_convert_count(const void* __restrict__ ei) {
    int e = blockIdx.x * blockDim.x + threadIdx.x;
    if (e >= NEDGES) return;
    int s, d;
    if (g_is64) {
        const long long* p = (const long long*)ei;
        s = (int)p[e];
        d = (int)p[NEDGES + e];
    } else {
        const int* p = (const int*)ei;
        s = p[e];
        d = p[NEDGES + e];
    }
    g_src[e] = s;
    g_dst[e] = d;
    atomicAdd(&g_deg[d], 1);
}

__global__ void k_dinv() {
    int i = blockIdx.x * blockDim.x + threadIdx.x;
    if (i < NNODES) g_dinv[i] = rsqrtf((float)g_deg[i] + 1.0f);  // +1 self loop
}

// ---------------- exclusive scan of g_deg -> g_rowptr ----------------
__global__ void k_scan_block() {
    __shared__ int s[1024];
    int t = threadIdx.x;
    int gi = blockIdx.x * 1024 + t;
    int v = (gi < NNODES) ? g_deg[gi] : 0;
    s[t] = v;
    __syncthreads();
#pragma unroll
    for (int off = 1; off < 1024; off <<= 1) {
        int a = (t >= off) ? s[t - off] : 0;
        __syncthreads();
        s[t] += a;
        __syncthreads();
    }
    if (gi <= NNODES) g_rowptr[gi] = s[t] - v;   // exclusive (local)
    if (t == 1023) g_bsum[blockIdx.x] = s[1023];
}

__global__ void k_scan_top() {
    if (threadIdx.x == 0) {
        int run = 0;
        for (int i = 0; i < NSCANB; i++) { int t = g_bsum[i]; g_bsum[i] = run; run += t; }
    }
}

__global__ void k_scan_add() {
    int i = blockIdx.x * blockDim.x + threadIdx.x;
    if (i < NNODES) {
        int rp = g_rowptr[i] + g_bsum[i >> 10];
        g_rowptr[i] = rp;
        g_cursor[i] = rp;
    }
    if (i == 0) g_rowptr[NNODES] = NEDGES;
}

// ---------------- fill CSR: packed (norm, src) per edge, grouped by dst ----------------
__global__ void k_fill() {
    int e = blockIdx.x * blockDim.x + threadIdx.x;
    if (e >= NEDGES) return;
    int s = g_src[e], d = g_dst[e];
    int pos = atomicAdd(&g_cursor[d], 1);
    float nrm = g_dinv[s] * g_dinv[d];
    g_csr[pos] = ((uint64_t)__float_as_uint(nrm) << 32) | (uint32_t)s;
}

// ---------------- GEMM: H[M,NO] = X[M,K] @ W[K,NO], f32x2 packed FMA ----------------
// 256 threads; CG = NO/16 column groups (warp-uniform); 2 rows per thread.
template <int K, int NO>
__global__ void __launch_bounds__(256) k_gemm(const float* __restrict__ X,
                                              const float* __restrict__ W,
                                              float* __restrict__ H) {
    constexpr int KT  = 32;
    constexpr int CG  = NO / 16;
    constexpr int TPG = 256 / CG;     // threads per column group (64 or 128)
    constexpr int RR  = TPG * 2;      // rows per block

    __shared__ __align__(16) float xs[RR * (KT + 1)];
    __shared__ __align__(16) float ws[KT * NO];

    const int tid  = threadIdx.x;
    const int r    = tid % TPG;
    const int cg   = tid / TPG;       // warp-uniform
    const int row0 = blockIdx.x * RR;
    const int rowA = row0 + r;
    const int rowB = row0 + r + TPG;

    uint64_t acc0[8], acc1[8];
#pragma unroll
    for (int p = 0; p < 8; p++) { acc0[p] = 0; acc1[p] = 0; }

    for (int kt = 0; kt < K; kt += KT) {
        for (int idx = tid; idx < RR * KT; idx += 256) {
            int rr = idx / KT, kk = idx % KT;
            int gr = row0 + rr;
            xs[rr * (KT + 1) + kk] = (gr < NNODES) ? X[(size_t)gr * K + kt + kk] : 0.0f;
        }
        for (int idx = tid; idx < KT * NO; idx += 256)
            ws[idx] = W[(size_t)kt * NO + idx];
        __syncthreads();

#pragma unroll
        for (int k = 0; k < KT; k++) {
            float xv0 = xs[r * (KT + 1) + k];
            float xv1 = xs[(r + TPG) * (KT + 1) + k];
            uint64_t xa, xb;
            asm("mov.b64 %0, {%1, %1};" : "=l"(xa) : "f"(xv0));
            asm("mov.b64 %0, {%1, %1};" : "=l"(xb) : "f"(xv1));
            const uint64_t* wrow = reinterpret_cast<const uint64_t*>(&ws[k * NO + cg * 16]);
#pragma unroll
            for (int p = 0; p < 8; p++) {
                uint64_t w = wrow[p];   // broadcast LDS.64 (same addr across warp)
                asm("fma.rn.f32x2 %0, %1, %2, %0;" : "+l"(acc0[p]) : "l"(xa), "l"(w));
                asm("fma.rn.f32x2 %0, %1, %2, %0;" : "+l"(acc1[p]) : "l"(xb), "l"(w));
            }
        }
        __syncthreads();
    }

    float v[16];
    if (rowA < NNODES) {
#pragma unroll
        for (int p = 0; p < 8; p++)
            asm("mov.b64 {%0, %1}, %2;" : "=f"(v[2*p]), "=f"(v[2*p+1]) : "l"(acc0[p]));
        float4* o = reinterpret_cast<float4*>(&H[(size_t)rowA * NO + cg * 16]);
        o[0] = make_float4(v[0], v[1], v[2], v[3]);
        o[1] = make_float4(v[4], v[5], v[6], v[7]);
        o[2] = make_float4(v[8], v[9], v[10], v[11]);
        o[3] = make_float4(v[12], v[13], v[14], v[15]);
    }
    if (rowB < NNODES) {
#pragma unroll
        for (int p = 0; p < 8; p++)
            asm("mov.b64 {%0, %1}, %2;" : "=f"(v[2*p]), "=f"(v[2*p+1]) : "l"(acc1[p]));
        float4* o = reinterpret_cast<float4*>(&H[(size_t)rowB * NO + cg * 16]);
        o[0] = make_float4(v[0], v[1], v[2], v[3]);
        o[1] = make_float4(v[4], v[5], v[6], v[7]);
        o[2] = make_float4(v[8], v[9], v[10], v[11]);
        o[3] = make_float4(v[12], v[13], v[14], v[15]);
    }
}

// ---------------- gather-side aggregation (no atomics) ----------------
// layer 1: warp per node, lane owns 2 cols (HID=64). Fuses self-loop, bias, ReLU.
__global__ void __launch_bounds__(256) k_agg1(const float* __restrict__ h1,
                                              const float* __restrict__ b1,
                                              float* __restrict__ h1r) {
    int node = blockIdx.x * 8 + (threadIdx.x >> 5);
    if (node >= NNODES) return;
    int lane = threadIdx.x & 31;
    int beg = g_rowptr[node], end = g_rowptr[node + 1];
    float dn = g_dinv[node];
    float sc = dn * dn;
    float2 hv = *reinterpret_cast<const float2*>(&h1[(size_t)node * HID + lane * 2]);
    float2 bv = *reinterpret_cast<const float2*>(&b1[lane * 2]);
    float2 acc = make_float2(fmaf(sc, hv.x, bv.x), fmaf(sc, hv.y, bv.y));
#pragma unroll 4
    for (int j = beg; j < end; j++) {
        uint64_t q = g_csr[j];                       // broadcast across warp
        int s = (int)(uint32_t)q;
        float nrm = __uint_as_float((uint32_t)(q >> 32));
        float2 vv = *reinterpret_cast<const float2*>(&h1[(size_t)s * HID + lane * 2]);
        acc.x = fmaf(nrm, vv.x, acc.x);
        acc.y = fmaf(nrm, vv.y, acc.y);
    }
    *reinterpret_cast<float2*>(&h1r[(size_t)node * HID + lane * 2]) =
        make_float2(fmaxf(acc.x, 0.0f), fmaxf(acc.y, 0.0f));
}

// layer 2: warp per node, lane owns 1 col (OUTD=32). Fuses self-loop + bias.
__global__ void __launch_bounds__(256) k_agg2(const float* __restrict__ h2,
                                              const float* __restrict__ b2,
                                              float* __restrict__ out) {
    int node = blockIdx.x * 8 + (threadIdx.x >> 5);
    if (node >= NNODES) return;
    int lane = threadIdx.x & 31;
    int beg = g_rowptr[node], end = g_rowptr[node + 1];
    float dn = g_dinv[node];
    float acc = fmaf(dn * dn, h2[(size_t)node * OUTD + lane], b2[lane]);
#pragma unroll 4
    for (int j = beg; j < end; j++) {
        uint64_t q = g_csr[j];
        int s = (int)(uint32_t)q;
        float nrm = __uint_as_float((uint32_t)(q >> 32));
        acc = fmaf(nrm, h2[(size_t)s * OUTD + lane], acc);
    }
    out[(size_t)node * OUTD + lane] = acc;
}

// ---------------- launch ----------------
extern "C" void kernel_launch(void* const* d_in, const int* in_sizes, int n_in,
                              void* d_out, int out_size) {
    const float* x  = (const float*)d_in[0];
    const void*  ei = d_in[1];
    const float* W1 = (const float*)d_in[2];
    const float* b1 = (const float*)d_in[3];
    const float* W2 = (const float*)d_in[4];
    const float* b2 = (const float*)d_in[5];
    float*       out = (float*)d_out;

    void *ph1, *ph1r, *ph2;
    cudaGetSymbolAddress(&ph1,  g_h1);
    cudaGetSymbolAddress(&ph1r, g_h1r);
    cudaGetSymbolAddress(&ph2,  g_h2);
    float* h1  = (float*)ph1;
    float* h1r = (float*)ph1r;
    float* h2  = (float*)ph2;

    const int NT = 256;
    const int EB = (NEDGES + NT - 1) / NT;
    const int NB = (NNODES + NT - 1) / NT;

    // graph normalization + CSR build
    k_detect<<<1, 32>>>((const int*)ei);
    k_zero_deg<<<NB, NT>>>();
    k_convert_count<<<EB, NT>>>(ei);
    k_dinv<<<NB, NT>>>();
    k_scan_block<<<NSCANB, 1024>>>();
    k_scan_top<<<1, 32>>>();
    k_scan_add<<<NB, NT>>>();
    k_fill<<<EB, NT>>>();

    // layer 1
    k_gemm<INDIM, HID><<<(NNODES + 127) / 128, NT>>>(x, W1, h1);
    k_agg1<<<(NNODES + 7) / 8, NT>>>(h1, b1, h1r);

    // layer 2
    k_gemm<HID, OUTD><<<(NNODES + 255) / 256, NT>>>(h1r, W2, h2);
    k_agg2<<<(NNODES + 7) / 8, NT>>>(h2, b2, out);
}